// round 14
// baseline (speedup 1.0000x reference)
#include <cuda_runtime.h>
#include <cuda_bf16.h>
#include <cstdint>

#define CO   256
#define CI   2048
#define HW   1024
#define NB   8

__device__ unsigned int   g_amax = 0u;
__device__ __nv_bfloat16  g_wq[CO * CI];
__device__ int8_t         g_wq8[CO * CI];
__device__ float          g_scale[CO];
__device__ float          g_bq[CO];

__device__ __forceinline__ uint32_t smem_u32(const void* p) {
    return static_cast<uint32_t>(__cvta_generic_to_shared(p));
}

__global__ void amax_kernel(const float* __restrict__ x, int n4) {
    const float4* x4 = reinterpret_cast<const float4*>(x);
    float m = 0.f;
    for (int i = blockIdx.x * blockDim.x + threadIdx.x; i < n4; i += gridDim.x * blockDim.x) {
        float4 v = x4[i];
        m = fmaxf(m, fmaxf(fmaxf(fabsf(v.x), fabsf(v.y)), fmaxf(fabsf(v.z), fabsf(v.w))));
    }
    #pragma unroll
    for (int o = 16; o; o >>= 1) m = fmaxf(m, __shfl_xor_sync(0xffffffffu, m, o));
    __shared__ float red[8];
    if ((threadIdx.x & 31) == 0) red[threadIdx.x >> 5] = m;
    __syncthreads();
    if (threadIdx.x < 8) {
        m = red[threadIdx.x];
        #pragma unroll
        for (int o = 4; o; o >>= 1) m = fmaxf(m, __shfl_xor_sync(0xffu, m, o));
        if (threadIdx.x == 0) atomicMax(&g_amax, __float_as_uint(m));
    }
}

// weights: per-channel quant -> bf16 ints AND packed int8
__global__ void wprep_kernel(const float* __restrict__ w, const float* __restrict__ bias) {
    const int co  = blockIdx.x;
    const int tid = threadIdx.x;
    const float* wr = w + (size_t)co * CI;
    float vals[8];
    float4 lo = *reinterpret_cast<const float4*>(wr + tid * 8);
    float4 hi = *reinterpret_cast<const float4*>(wr + tid * 8 + 4);
    vals[0] = lo.x; vals[1] = lo.y; vals[2] = lo.z; vals[3] = lo.w;
    vals[4] = hi.x; vals[5] = hi.y; vals[6] = hi.z; vals[7] = hi.w;

    float m = 0.f;
    #pragma unroll
    for (int j = 0; j < 8; j++) m = fmaxf(m, fabsf(vals[j]));
    #pragma unroll
    for (int o = 16; o; o >>= 1) m = fmaxf(m, __shfl_xor_sync(0xffffffffu, m, o));
    __shared__ float red[8];
    __shared__ float s_sw_sh;
    if ((tid & 31) == 0) red[tid >> 5] = m;
    __syncthreads();
    if (tid == 0) {
        float mm = red[0];
        #pragma unroll
        for (int i = 1; i < 8; i++) mm = fmaxf(mm, red[i]);
        float s_w = fmaxf(mm, 1e-8f) / 127.f;
        s_sw_sh = s_w;
        float s_a = fmaxf(__uint_as_float(g_amax), 1e-8f) / 127.f;
        float s_b = s_a * s_w;
        g_scale[co] = s_b;
        g_bq[co]    = rintf(bias[co] / s_b) * s_b;
    }
    __syncthreads();
    const float inv_sw = 1.f / s_sw_sh;

    int q[8];
    #pragma unroll
    for (int j = 0; j < 8; j++) {
        int s = __float2int_rn(vals[j] * inv_sw);
        q[j] = max(-128, min(127, s));
    }
    // bf16 ints
    uint4 pk;
    __nv_bfloat162 p0 = __floats2bfloat162_rn((float)q[0], (float)q[1]);
    __nv_bfloat162 p1 = __floats2bfloat162_rn((float)q[2], (float)q[3]);
    __nv_bfloat162 p2 = __floats2bfloat162_rn((float)q[4], (float)q[5]);
    __nv_bfloat162 p3 = __floats2bfloat162_rn((float)q[6], (float)q[7]);
    pk.x = *reinterpret_cast<uint32_t*>(&p0);
    pk.y = *reinterpret_cast<uint32_t*>(&p1);
    pk.z = *reinterpret_cast<uint32_t*>(&p2);
    pk.w = *reinterpret_cast<uint32_t*>(&p3);
    *reinterpret_cast<uint4*>(g_wq + (size_t)co * CI + tid * 8) = pk;
    // packed int8
    uint32_t w0 = __byte_perm(__byte_perm((unsigned)q[0], (unsigned)q[1], 0x0040),
                              __byte_perm((unsigned)q[2], (unsigned)q[3], 0x0040), 0x5410);
    uint32_t w1 = __byte_perm(__byte_perm((unsigned)q[4], (unsigned)q[5], 0x0040),
                              __byte_perm((unsigned)q[6], (unsigned)q[7], 0x0040), 0x5410);
    *reinterpret_cast<uint2*>(g_wq8 + (size_t)co * CI + tid * 8) = make_uint2(w0, w1);
}

// ---- hybrid GEMM: R2 HMMA (256 thr) + 2 dp4a warps (64 thr) ----
#define BM    128
#define BN    64
#define BK    32
#define KT_N  (CI / BK)   // 64
#define KD_IT 54          // HMMA-only k iterations for hw[0:32] strip
#define KD    (KD_IT * BK)        // 1728
#define KDP   (CI - KD)           // 320
#define ASTR  40     // A smem row stride (bf16 elems)
#define BSTR  72     // B smem row stride (bf16 elems)

#define BAR_HMMA() asm volatile("bar.sync 1, 256;" ::: "memory")
#define BAR_ALL()  asm volatile("bar.sync 0, 320;" ::: "memory")

__global__ __launch_bounds__(320, 2) void gemm_kernel(const float* __restrict__ x,
                                                      float* __restrict__ out) {
    __shared__ __align__(16) __nv_bfloat16 As[2][BM * ASTR];
    __shared__ __align__(16) __nv_bfloat16 Bs[2][BK * BSTR];
    __shared__ __align__(16) int Cd[BM][32];          // dp4a partials, hw[0:32]

    const int tid  = threadIdx.x;
    const int lane = tid & 31;
    const int warp = tid >> 5;

    const int tileM = blockIdx.x;            // 0..1 (fastest -> L2 x reuse)
    const int tileN = blockIdx.y;            // 0..127
    const int b     = tileN >> 4;
    const int hw0   = (tileN & 15) * BN;
    const float* xb = x + (size_t)b * CI * HW + hw0;

    const float s_a    = fmaxf(__uint_as_float(g_amax), 1e-8f) / 127.f;
    const float inv_sa = 1.f / s_a;
    const float MAGIC  = 12582912.f;   // 1.5 * 2^23

    if (tid >= 256) {
        // ================= dp4a warps: hw[0:32], k[KD:2048) =================
        const int t2    = tid - 256;          // 0..63
        const int co0L  = (t2 & 7) * 16;      // 16 co rows
        const int hwL   = (t2 >> 3) * 4;      // 4 hw cols
        const int8_t* w8 = g_wq8 + (size_t)(tileM * BM + co0L) * CI + KD;
        const float*  xp = xb + (size_t)KD * HW + hwL;

        int acc[16][4];
        #pragma unroll
        for (int c = 0; c < 16; c++)
            #pragma unroll
            for (int h = 0; h < 4; h++) acc[c][h] = 0;

        for (int k4 = 0; k4 < KDP / 4; k4++) {
            float4 xv[4];
            #pragma unroll
            for (int r = 0; r < 4; r++)
                xv[r] = *reinterpret_cast<const float4*>(xp + (size_t)(k4 * 4 + r) * HW);
            int xw[4];
            #pragma unroll
            for (int h = 0; h < 4; h++) {
                const float* f0 = reinterpret_cast<const float*>(&xv[0]);
                const float* f1 = reinterpret_cast<const float*>(&xv[1]);
                const float* f2 = reinterpret_cast<const float*>(&xv[2]);
                const float* f3 = reinterpret_cast<const float*>(&xv[3]);
                int s0 = __float2int_rn(f0[h] * inv_sa);
                int s1 = __float2int_rn(f1[h] * inv_sa);
                int s2 = __float2int_rn(f2[h] * inv_sa);
                int s3 = __float2int_rn(f3[h] * inv_sa);
                xw[h] = (int)__byte_perm(__byte_perm((unsigned)s0, (unsigned)s1, 0x0040),
                                         __byte_perm((unsigned)s2, (unsigned)s3, 0x0040),
                                         0x5410);
            }
            #pragma unroll
            for (int c = 0; c < 16; c++) {
                int wv = *reinterpret_cast<const int*>(w8 + (size_t)c * CI + k4 * 4);
                #pragma unroll
                for (int h = 0; h < 4; h++)
                    acc[c][h] = __dp4a(xw[h], wv, acc[c][h]);
            }
        }
        #pragma unroll
        for (int c = 0; c < 16; c++)
            *reinterpret_cast<int4*>(&Cd[co0L + c][hwL]) =
                make_int4(acc[c][0], acc[c][1], acc[c][2], acc[c][3]);
        BAR_ALL();
        return;
    }

    // ================= HMMA warps (0-7): R2 path =================
    const int wm = warp >> 1;   // 0..3 -> 32 co rows
    const int wn = warp & 1;    // 0..1 -> 32 hw cols

    const int brow = tid >> 4;          // 0..15, +16
    const int bcol = (tid & 15) * 4;    // 0..60
    const int arow = tid >> 2;          // 0..63, +64
    const int acol = (tid & 3) * 8;     // 0,8,16,24

    const __nv_bfloat16* wq = g_wq + (size_t)(tileM * BM) * CI;

    float4 bReg[2];

    auto loadB = [&](int kt) {
        const float* xp = xb + (size_t)(kt * BK) * HW;
        bReg[0] = *reinterpret_cast<const float4*>(xp + (size_t)brow * HW + bcol);
        bReg[1] = *reinterpret_cast<const float4*>(xp + (size_t)(brow + 16) * HW + bcol);
    };
    auto storeB = [&](int st) {
        #pragma unroll
        for (int i = 0; i < 2; i++) {
            float4 v = bReg[i];
            float q0 = fmaf(v.x, inv_sa, MAGIC) - MAGIC;
            float q1 = fmaf(v.y, inv_sa, MAGIC) - MAGIC;
            float q2 = fmaf(v.z, inv_sa, MAGIC) - MAGIC;
            float q3 = fmaf(v.w, inv_sa, MAGIC) - MAGIC;
            __nv_bfloat162* dst =
                reinterpret_cast<__nv_bfloat162*>(&Bs[st][(brow + 16 * i) * BSTR + bcol]);
            dst[0] = __floats2bfloat162_rn(q0, q1);
            dst[1] = __floats2bfloat162_rn(q2, q3);
        }
    };
    auto loadA = [&](int kt, int st) {
        const __nv_bfloat16* wp = wq + kt * BK;
        #pragma unroll
        for (int i = 0; i < 2; i++) {
            uint32_t dst = smem_u32(&As[st][(arow + 64 * i) * ASTR + acol]);
            const void* src = wp + (size_t)(arow + 64 * i) * CI + acol;
            asm volatile("cp.async.cg.shared.global [%0], [%1], 16;\n" :: "r"(dst), "l"(src));
        }
        asm volatile("cp.async.commit_group;\n");
    };

    loadA(0, 0);
    loadB(0);
    storeB(0);
    asm volatile("cp.async.wait_group 0;\n");
    BAR_HMMA();

    float acc[2][4][4];
    #pragma unroll
    for (int mt = 0; mt < 2; mt++)
        #pragma unroll
        for (int nt = 0; nt < 4; nt++)
            #pragma unroll
            for (int r = 0; r < 4; r++) acc[mt][nt][r] = 0.f;

    for (int kt = 0; kt < KT_N; kt++) {
        const int cur = kt & 1;
        const int nxt = cur ^ 1;
        if (kt + 1 < KT_N) {
            loadA(kt + 1, nxt);
            loadB(kt + 1);
        }

        const bool active = (wn == 1) || (kt < KD_IT);
        if (active) {
            #pragma unroll
            for (int kk = 0; kk < 2; kk++) {
                uint32_t a[2][4];
                #pragma unroll
                for (int mt = 0; mt < 2; mt++) {
                    int mr = wm * 32 + mt * 16 + (lane & 15);
                    int kc = kk * 16 + (lane >> 4) * 8;
                    uint32_t addr = smem_u32(&As[cur][mr * ASTR + kc]);
                    asm volatile("ldmatrix.sync.aligned.m8n8.x4.shared.b16 {%0,%1,%2,%3}, [%4];"
                                 : "=r"(a[mt][0]), "=r"(a[mt][1]), "=r"(a[mt][2]), "=r"(a[mt][3])
                                 : "r"(addr));
                }
                uint32_t bf[2][4];
                #pragma unroll
                for (int np = 0; np < 2; np++) {
                    int kr = kk * 16 + (lane & 15);
                    int nc = wn * 32 + np * 16 + (lane >> 4) * 8;
                    uint32_t addr = smem_u32(&Bs[cur][kr * BSTR + nc]);
                    asm volatile("ldmatrix.sync.aligned.m8n8.x4.trans.shared.b16 {%0,%1,%2,%3}, [%4];"
                                 : "=r"(bf[np][0]), "=r"(bf[np][1]), "=r"(bf[np][2]), "=r"(bf[np][3])
                                 : "r"(addr));
                }
                #pragma unroll
                for (int mt = 0; mt < 2; mt++) {
                    #pragma unroll
                    for (int nt = 0; nt < 4; nt++) {
                        uint32_t b0 = bf[nt >> 1][(nt & 1) * 2 + 0];
                        uint32_t b1 = bf[nt >> 1][(nt & 1) * 2 + 1];
                        asm volatile(
                            "mma.sync.aligned.m16n8k16.row.col.f32.bf16.bf16.f32 "
                            "{%0,%1,%2,%3}, {%4,%5,%6,%7}, {%8,%9}, {%0,%1,%2,%3};"
                            : "+f"(acc[mt][nt][0]), "+f"(acc[mt][nt][1]),
                              "+f"(acc[mt][nt][2]), "+f"(acc[mt][nt][3])
                            : "r"(a[mt][0]), "r"(a[mt][1]), "r"(a[mt][2]), "r"(a[mt][3]),
                              "r"(b0), "r"(b1));
                    }
                }
            }
        }

        if (kt + 1 < KT_N) {
            storeB(nxt);
            asm volatile("cp.async.wait_group 0;\n");
        }
        BAR_HMMA();
    }

    BAR_ALL();   // dp4a partials visible in Cd

    // epilogue (wn==0 merges dp4a partials)
    #pragma unroll
    for (int mt = 0; mt < 2; mt++) {
        int coL = wm * 32 + mt * 16 + (lane >> 2);
        int co0 = tileM * BM + coL;
        float s0 = g_scale[co0],     q0 = g_bq[co0];
        float s1 = g_scale[co0 + 8], q1 = g_bq[co0 + 8];
        #pragma unroll
        for (int nt = 0; nt < 4; nt++) {
            int hwL = wn * 32 + nt * 8 + (lane & 3) * 2;
            float a0 = acc[mt][nt][0], a1 = acc[mt][nt][1];
            float a2 = acc[mt][nt][2], a3 = acc[mt][nt][3];
            if (wn == 0) {
                a0 += (float)Cd[coL][hwL];
                a1 += (float)Cd[coL][hwL + 1];
                a2 += (float)Cd[coL + 8][hwL];
                a3 += (float)Cd[coL + 8][hwL + 1];
            }
            float* o = out + (size_t)b * CO * HW + (size_t)co0 * HW + hw0 + hwL;
            *reinterpret_cast<float2*>(o) = make_float2(a0 * s0 + q0, a1 * s0 + q0);
            *reinterpret_cast<float2*>(o + 8 * HW) = make_float2(a2 * s1 + q1, a3 * s1 + q1);
        }
    }
}

extern "C" void kernel_launch(void* const* d_in, const int* in_sizes, int n_in,
                              void* d_out, int out_size) {
    const float* x    = (const float*)d_in[0];
    const float* w    = (const float*)d_in[1];
    const float* bias = (const float*)d_in[2];
    float* out        = (float*)d_out;

    const int n4 = (NB * CI * HW) / 4;
    amax_kernel<<<1024, 256>>>(x, n4);
    wprep_kernel<<<CO, 256>>>(w, bias);
    dim3 grid(2, 128);
    gemm_kernel<<<grid, 320>>>(x, out);
}

// round 15
// speedup vs baseline: 1.6074x; 1.6074x over previous
#include <cuda_runtime.h>
#include <cuda_bf16.h>
#include <cstdint>

#define CO   256
#define CI   2048
#define HW   1024
#define NB   8

__device__ unsigned int   g_amax = 0u;
__device__ __nv_bfloat16  g_wq[CO * CI];
__device__ float          g_scale[CO];
__device__ float          g_bq[CO];

__device__ __forceinline__ uint32_t smem_u32(const void* p) {
    return static_cast<uint32_t>(__cvta_generic_to_shared(p));
}

// ---- amax: 64MB scan, MLP=4, sign-strip on ALU pipe ----
__global__ __launch_bounds__(512, 2) void amax_kernel(const float* __restrict__ x) {
    const uint4* x4 = reinterpret_cast<const uint4*>(x);
    const int    i0 = blockIdx.x * blockDim.x + threadIdx.x;
    const int    stride = gridDim.x * blockDim.x;    // 524288 = (8M/4)/4

    uint4 v[4];
    #pragma unroll
    for (int j = 0; j < 4; j++) v[j] = x4[i0 + j * stride];

    uint32_t m = 0;
    #pragma unroll
    for (int j = 0; j < 4; j++) {
        m = max(m, v[j].x & 0x7fffffffu);
        m = max(m, v[j].y & 0x7fffffffu);
        m = max(m, v[j].z & 0x7fffffffu);
        m = max(m, v[j].w & 0x7fffffffu);
    }
    // non-negative float bits compare like uints
    #pragma unroll
    for (int o = 16; o; o >>= 1) m = max(m, __shfl_xor_sync(0xffffffffu, m, o));
    __shared__ uint32_t red[16];
    if ((threadIdx.x & 31) == 0) red[threadIdx.x >> 5] = m;
    __syncthreads();
    if (threadIdx.x < 16) {
        m = red[threadIdx.x];
        #pragma unroll
        for (int o = 8; o; o >>= 1) m = max(m, __shfl_xor_sync(0xffffu, m, o));
        if (threadIdx.x == 0) atomicMax(&g_amax, m);
    }
}

__global__ void wprep_kernel(const float* __restrict__ w, const float* __restrict__ bias) {
    const int co  = blockIdx.x;
    const int tid = threadIdx.x;
    const float* wr = w + (size_t)co * CI;
    float vals[8];
    float m = 0.f;
    #pragma unroll
    for (int j = 0; j < 8; j++) {
        vals[j] = wr[tid + 256 * j];
        m = fmaxf(m, fabsf(vals[j]));
    }
    #pragma unroll
    for (int o = 16; o; o >>= 1) m = fmaxf(m, __shfl_xor_sync(0xffffffffu, m, o));
    __shared__ float red[8];
    __shared__ float s_sw_sh;
    if ((tid & 31) == 0) red[tid >> 5] = m;
    __syncthreads();
    if (tid == 0) {
        float mm = red[0];
        #pragma unroll
        for (int i = 1; i < 8; i++) mm = fmaxf(mm, red[i]);
        float s_w = fmaxf(mm, 1e-8f) / 127.f;
        s_sw_sh = s_w;
        float s_a = fmaxf(__uint_as_float(g_amax), 1e-8f) / 127.f;
        float s_b = s_a * s_w;
        g_scale[co] = s_b;
        g_bq[co]    = rintf(bias[co] / s_b) * s_b;
    }
    __syncthreads();
    const float s_w = s_sw_sh;
    #pragma unroll
    for (int j = 0; j < 8; j++) {
        float q = fminf(fmaxf(rintf(vals[j] / s_w), -128.f), 127.f);
        g_wq[(size_t)co * CI + tid + 256 * j] = __float2bfloat16(q);
    }
}

// ---------------- GEMM: R2 exactly — BM=128, BN=64, BK=32, double-buffered ----------------
#define BM   128
#define BN   64
#define BK   32
#define ASTR 40     // A smem row stride (bf16 elems)
#define BSTR 72     // B smem row stride (bf16 elems)

__global__ __launch_bounds__(256, 2) void gemm_kernel(const float* __restrict__ x,
                                                      float* __restrict__ out) {
    __shared__ __align__(16) __nv_bfloat16 As[2][BM * ASTR];
    __shared__ __align__(16) __nv_bfloat16 Bs[2][BK * BSTR];

    const int tid  = threadIdx.x;
    const int lane = tid & 31;
    const int warp = tid >> 5;
    const int wm   = warp >> 1;   // 0..3 -> 32 rows each
    const int wn   = warp & 1;    // 0..1 -> 32 cols each

    const int tileM = blockIdx.x;            // 0..1  (fastest -> L2 x reuse)
    const int tileN = blockIdx.y;            // 0..127
    const int b     = tileN >> 4;
    const int hw0   = (tileN & 15) * BN;
    const float* xb = x + (size_t)b * CI * HW + hw0;

    const float s_a    = fmaxf(__uint_as_float(g_amax), 1e-8f) / 127.f;
    const float inv_sa = 1.f / s_a;

    const int brow = tid >> 4;          // 0..15, +16
    const int bcol = (tid & 15) * 4;    // 0..60
    const int arow = tid >> 2;          // 0..63, +64
    const int acol = (tid & 3) * 8;     // 0,8,16,24

    const __nv_bfloat16* wq = g_wq + (size_t)(tileM * BM) * CI;

    float4 bReg[2];

    auto loadB = [&](int kt) {
        const float* xp = xb + (size_t)(kt * BK) * HW;
        bReg[0] = *reinterpret_cast<const float4*>(xp + (size_t)brow * HW + bcol);
        bReg[1] = *reinterpret_cast<const float4*>(xp + (size_t)(brow + 16) * HW + bcol);
    };
    auto storeB = [&](int st) {
        #pragma unroll
        for (int i = 0; i < 2; i++) {
            float qx = fminf(fmaxf(rintf(bReg[i].x * inv_sa), -128.f), 127.f);
            float qy = fminf(fmaxf(rintf(bReg[i].y * inv_sa), -128.f), 127.f);
            float qz = fminf(fmaxf(rintf(bReg[i].z * inv_sa), -128.f), 127.f);
            float qw = fminf(fmaxf(rintf(bReg[i].w * inv_sa), -128.f), 127.f);
            __nv_bfloat162* dst =
                reinterpret_cast<__nv_bfloat162*>(&Bs[st][(brow + 16 * i) * BSTR + bcol]);
            dst[0] = __floats2bfloat162_rn(qx, qy);
            dst[1] = __floats2bfloat162_rn(qz, qw);
        }
    };
    auto loadA = [&](int kt, int st) {
        const __nv_bfloat16* wp = wq + kt * BK;
        #pragma unroll
        for (int i = 0; i < 2; i++) {
            uint32_t dst = smem_u32(&As[st][(arow + 64 * i) * ASTR + acol]);
            const void* src = wp + (size_t)(arow + 64 * i) * CI + acol;
            asm volatile("cp.async.cg.shared.global [%0], [%1], 16;\n" :: "r"(dst), "l"(src));
        }
        asm volatile("cp.async.commit_group;\n");
    };

    // prologue: stage 0
    loadA(0, 0);
    loadB(0);
    storeB(0);
    asm volatile("cp.async.wait_group 0;\n");
    __syncthreads();

    float acc[2][4][4];
    #pragma unroll
    for (int mt = 0; mt < 2; mt++)
        #pragma unroll
        for (int nt = 0; nt < 4; nt++)
            #pragma unroll
            for (int r = 0; r < 4; r++) acc[mt][nt][r] = 0.f;

    const int KT = CI / BK;  // 64
    for (int kt = 0; kt < KT; kt++) {
        const int cur = kt & 1;
        const int nxt = cur ^ 1;
        if (kt + 1 < KT) {
            loadA(kt + 1, nxt);
            loadB(kt + 1);
        }

        #pragma unroll
        for (int kk = 0; kk < 2; kk++) {
            uint32_t a[2][4];
            #pragma unroll
            for (int mt = 0; mt < 2; mt++) {
                int mr = wm * 32 + mt * 16 + (lane & 15);
                int kc = kk * 16 + (lane >> 4) * 8;
                uint32_t addr = smem_u32(&As[cur][mr * ASTR + kc]);
                asm volatile("ldmatrix.sync.aligned.m8n8.x4.shared.b16 {%0,%1,%2,%3}, [%4];"
                             : "=r"(a[mt][0]), "=r"(a[mt][1]), "=r"(a[mt][2]), "=r"(a[mt][3])
                             : "r"(addr));
            }
            uint32_t bf[2][4];
            #pragma unroll
            for (int np = 0; np < 2; np++) {
                int kr = kk * 16 + (lane & 15);
                int nc = wn * 32 + np * 16 + (lane >> 4) * 8;
                uint32_t addr = smem_u32(&Bs[cur][kr * BSTR + nc]);
                asm volatile("ldmatrix.sync.aligned.m8n8.x4.trans.shared.b16 {%0,%1,%2,%3}, [%4];"
                             : "=r"(bf[np][0]), "=r"(bf[np][1]), "=r"(bf[np][2]), "=r"(bf[np][3])
                             : "r"(addr));
            }
            #pragma unroll
            for (int mt = 0; mt < 2; mt++) {
                #pragma unroll
                for (int nt = 0; nt < 4; nt++) {
                    uint32_t b0 = bf[nt >> 1][(nt & 1) * 2 + 0];
                    uint32_t b1 = bf[nt >> 1][(nt & 1) * 2 + 1];
                    asm volatile(
                        "mma.sync.aligned.m16n8k16.row.col.f32.bf16.bf16.f32 "
                        "{%0,%1,%2,%3}, {%4,%5,%6,%7}, {%8,%9}, {%0,%1,%2,%3};"
                        : "+f"(acc[mt][nt][0]), "+f"(acc[mt][nt][1]),
                          "+f"(acc[mt][nt][2]), "+f"(acc[mt][nt][3])
                        : "r"(a[mt][0]), "r"(a[mt][1]), "r"(a[mt][2]), "r"(a[mt][3]),
                          "r"(b0), "r"(b1));
                }
            }
        }

        if (kt + 1 < KT) {
            storeB(nxt);
            asm volatile("cp.async.wait_group 0;\n");
        }
        __syncthreads();
    }

    // epilogue
    #pragma unroll
    for (int mt = 0; mt < 2; mt++) {
        int co0 = tileM * BM + wm * 32 + mt * 16 + (lane >> 2);
        float s0 = g_scale[co0],     q0 = g_bq[co0];
        float s1 = g_scale[co0 + 8], q1 = g_bq[co0 + 8];
        #pragma unroll
        for (int nt = 0; nt < 4; nt++) {
            int hw = hw0 + wn * 32 + nt * 8 + (lane & 3) * 2;
            float* o = out + (size_t)b * CO * HW + (size_t)co0 * HW + hw;
            float2 v0 = make_float2(acc[mt][nt][0] * s0 + q0, acc[mt][nt][1] * s0 + q0);
            float2 v1 = make_float2(acc[mt][nt][2] * s1 + q1, acc[mt][nt][3] * s1 + q1);
            *reinterpret_cast<float2*>(o) = v0;
            *reinterpret_cast<float2*>(o + 8 * HW) = v1;
        }
    }
}

extern "C" void kernel_launch(void* const* d_in, const int* in_sizes, int n_in,
                              void* d_out, int out_size) {
    const float* x    = (const float*)d_in[0];
    const float* w    = (const float*)d_in[1];
    const float* bias = (const float*)d_in[2];
    float* out        = (float*)d_out;

    // 8M floats = 2M uint4; 1024 blocks x 512 threads x 4 uint4 each
    amax_kernel<<<1024, 512>>>(x);
    wprep_kernel<<<CO, 256>>>(w, bias);
    dim3 grid(2, 128);
    gemm_kernel<<<grid, 256>>>(x, out);
}